// round 15
// baseline (speedup 1.0000x reference)
#include <cuda_runtime.h>
#include <math.h>
#include <stdint.h>

#define IMG_W 1024
#define IMG_H 1024
#define IMG_B 8
#define IMG_HW (IMG_H * IMG_W)

#define TX 32
#define TY 32
#define NTHR 512
#define NPAIR 4
#define BTX 32
#define BTY 16
#define NBLOCKS_BACK ((IMG_W / BTX) * (IMG_H / BTY) * 2)

// ---------------------------------------------------------------------------
// Scratch (allocation-free rule: __device__ globals; zero-initialized)
// ---------------------------------------------------------------------------
__device__ float2 g_sup2[(size_t)NPAIR * IMG_HW];
__device__ unsigned int g_max_bits;   // reset by last back block each launch
__device__ unsigned int g_done;

__device__ __forceinline__ int refl(int i, int n) {
    if (i < 0) i = -i;
    if (i >= n) i = 2 * n - 2 - i;
    return i;
}

// fast sigmoid (smooth output path only)
__device__ __forceinline__ float sigm(float x) {
    float e = __expf(-x);
    float d = 1.0f + e;
    float r; asm("rcp.approx.f32 %0, %1;" : "=f"(r) : "f"(d));
    return r;
}

// packed helpers for the back kernel
__device__ __forceinline__ uint64_t f2add(uint64_t a, uint64_t b) {
    uint64_t r; asm("add.rn.f32x2 %0, %1, %2;" : "=l"(r) : "l"(a), "l"(b)); return r;
}
__device__ __forceinline__ uint64_t pack2(float lo, float hi) {
    return ((uint64_t)__float_as_uint(hi) << 32) | (uint64_t)__float_as_uint(lo);
}
__device__ __forceinline__ float plo(uint64_t v) { return __uint_as_float((unsigned)v); }
__device__ __forceinline__ float phi(uint64_t v) { return __uint_as_float((unsigned)(v >> 32)); }

// ---------------------------------------------------------------------------
// Exact fp32 -> Q0.27 u32 (round-to-nearest; mantissa shift, no fp rounding)
// ---------------------------------------------------------------------------
__device__ __forceinline__ unsigned q27(float v) {
    const unsigned bits = __float_as_uint(v);       // v >= 0
    const int e = (int)(bits >> 23);
    const unsigned m = (bits & 0x7fffffu) | 0x800000u;
    const int sh = e - 123;                         // v*2^27 = m * 2^sh
    if (sh >= 0) return m << sh;                    // v < 1 -> sh <= 3
    const int k = -sh;
    return (k < 32) ? ((m + (1u << (k - 1))) >> k) : 0u;
}

// Exact fp32 weight -> Q0.32 u32 (weights have ulp >= 2^-29: exact)
__device__ __forceinline__ unsigned wq32(float w) {
    const unsigned bits = __float_as_uint(w);
    const unsigned m = (bits & 0x7fffffu) | 0x800000u;
    const int sh = (int)(bits >> 23) - 118;
    return m << sh;
}

// round(tan(22.5 deg) * 2^32)
#define T1U 1779033704u

// ---------------------------------------------------------------------------
// Shared overlay (bytes), peak 34688 (static):
//   img (40x40 u64 = [40][80] u32, 12800) @ 0      live S1-S2
//   row (40x36 u64 = [40][72] u32, 11520) @ 12800  live S2-S3
//   sm  (36x36 u64 = [36][72] u32, 10368) @ 24320  live S3-SD
//   g2  (34x34 x 2 lanes u64,      18496) @ 0      live SD-SE
//   bin (34x34 u8,                  1156) @ 18496  live SD-SE
// ---------------------------------------------------------------------------
#define OFF_IMG 0
#define OFF_ROW 12800
#define OFF_SM  24320
#define OFF_G2  0
#define OFF_BIN 18496
#define SBUF_SZ 34688

// ---------------------------------------------------------------------------
// Fused front (integer pipeline, lane-split for low register pressure)
// ---------------------------------------------------------------------------
__global__ __launch_bounds__(NTHR, 4) void fused_front_kernel(const float* __restrict__ img) {
    __shared__ __align__(16) unsigned char sbuf[SBUF_SZ];
    __shared__ float smax[NTHR / 32];

    uint64_t (*s_img)[40] = (uint64_t(*)[40])(sbuf + OFF_IMG);     // packed store
    unsigned (*s_img32)[80] = (unsigned(*)[80])(sbuf + OFF_IMG);   // lane reads
    unsigned (*s_row32)[72] = (unsigned(*)[72])(sbuf + OFF_ROW);
    unsigned (*s_sm32 )[72] = (unsigned(*)[72])(sbuf + OFF_SM);
    uint64_t* s_g2_64 = (uint64_t*)(sbuf + OFF_G2);                // [(jy*34+jx)*2+c]
    unsigned char (*s_bin)[34] = (unsigned char(*)[34])(sbuf + OFF_BIN);

    const int x0 = blockIdx.x * TX;
    const int y0 = blockIdx.y * TY;
    const int p  = blockIdx.z;
    const float* p0 = img + (size_t)(2 * p)     * IMG_HW;
    const float* p1 = img + (size_t)(2 * p + 1) * IMG_HW;
    const int tid = threadIdx.x;

    const float w5[5] = {0.054488684549640294f, 0.24420134200323337f,
                         0.4026199468935272f,  0.24420134200323337f,
                         0.054488684549640294f};
    unsigned W[5];
#pragma unroll
    for (int k = 0; k < 5; k++) W[k] = wq32(w5[k]);

    // ---- S1: load + quantize image tile 40x40 (reflect once) ----
#pragma unroll 2
    for (int i = tid; i < 40 * 40; i += NTHR) {
        const int yy = i / 40, xx = i - yy * 40;
        const int gx = refl(x0 - 4 + xx, IMG_W);
        const int gy = refl(y0 - 4 + yy, IMG_H);
        const int gi = gy * IMG_W + gx;
        const unsigned a = q27(p0[gi]);
        const unsigned b = q27(p1[gi]);
        s_img[yy][xx] = ((uint64_t)b << 32) | a;
    }
    __syncthreads();

    // ---- S2: row gaussian (x): per-lane u32 MACs, round to Q0.29 ----
#pragma unroll 2
    for (int i = tid; i < 40 * 36; i += NTHR) {
        const int ry = i / 36, rx = i - ry * 36;
#pragma unroll
        for (int c = 0; c < 2; c++) {
            uint64_t acc = 0;
#pragma unroll
            for (int k = 0; k < 5; k++)
                acc += (uint64_t)W[k] * s_img32[ry][2 * (rx + k) + c];
            s_row32[ry][2 * rx + c] = (unsigned)((acc + (1u << 29)) >> 30);
        }
    }
    __syncthreads();

    // ---- S3: column gaussian (y): per-lane MACs, round to Q0.29 ----
#pragma unroll 2
    for (int i = tid; i < 36 * 36; i += NTHR) {
        const int sy = i / 36, sx = i - sy * 36;
#pragma unroll
        for (int c = 0; c < 2; c++) {
            uint64_t acc = 0;
#pragma unroll
            for (int k = 0; k < 5; k++)
                acc += (uint64_t)W[k] * s_row32[sy + k][2 * sx + c];
            s_sm32[sy][2 * sx + c] = (unsigned)((acc + (1u << 31)) >> 32);
        }
    }
    __syncthreads();

    // ---- SD: sobel + g2 + bins (per-lane, exact int32/int64) ----
#pragma unroll 2
    for (int i = tid; i < 34 * 34; i += NTHR) {
        const int jy = i / 34, jx = i - jy * 34;
        const bool interior = (jy >= 1 && jy <= TY && jx >= 1 && jx <= TX);
        unsigned char packed_bins = 0;
#pragma unroll
        for (int c = 0; c < 2; c++) {
            const int v00 = (int)s_sm32[jy + 0][2 * (jx + 0) + c];
            const int v01 = (int)s_sm32[jy + 0][2 * (jx + 1) + c];
            const int v02 = (int)s_sm32[jy + 0][2 * (jx + 2) + c];
            const int v10 = (int)s_sm32[jy + 1][2 * (jx + 0) + c];
            const int v12 = (int)s_sm32[jy + 1][2 * (jx + 2) + c];
            const int v20 = (int)s_sm32[jy + 2][2 * (jx + 0) + c];
            const int v21 = (int)s_sm32[jy + 2][2 * (jx + 1) + c];
            const int v22 = (int)s_sm32[jy + 2][2 * (jx + 2) + c];

            const int gx = (v02 - v00) + 2 * (v12 - v10) + (v22 - v20);
            const int gy = (v00 + 2 * v01 + v02) - (v20 + 2 * v21 + v22);

            s_g2_64[(jy * 34 + jx) * 2 + c] =
                (uint64_t)((long long)gx * gx + (long long)gy * gy);

            if (interior) {
                const unsigned ax = (unsigned)(gx < 0 ? -gx : gx);
                const unsigned ay = (unsigned)(gy < 0 ? -gy : gy);
                unsigned char bin;
                if (((uint64_t)ay << 32) < (uint64_t)T1U * ax)       bin = 0; // E/W
                else if (((uint64_t)ax << 32) <= (uint64_t)T1U * ay) bin = 2; // N/S
                else bin = ((gx > 0) == (gy > 0)) ? 1 : 3;                    // SW/NE : SE/NW
                packed_bins |= bin << (2 * c);
            }
        }
        if (interior) s_bin[jy][jx] = packed_bins;
    }
    __syncthreads();

    // ---- SE: NMS (exact u64 compares) + sup + block max ----
    const int tx = tid & (TX - 1);
    const int ty = tid >> 5;   // 0..15

    float vmax = 0.0f;
#pragma unroll
    for (int half = 0; half < 2; half++) {
        const int oy = ty + half * 16;
        const unsigned char pb2 = s_bin[oy + 1][tx + 1];

        float sup[2];
#pragma unroll
        for (int comp = 0; comp < 2; comp++) {
            const int bin = (pb2 >> (2 * comp)) & 3;
            int ay, ax_, by, bx_;
            if (bin == 0)      { ay = oy + 1; ax_ = tx + 2; by = oy + 1; bx_ = tx + 0; } // E,W
            else if (bin == 2) { ay = oy + 0; ax_ = tx + 1; by = oy + 2; bx_ = tx + 1; } // N,S
            else if (bin == 1) { ay = oy + 2; ax_ = tx + 0; by = oy + 0; bx_ = tx + 2; } // SW,NE
            else               { ay = oy + 2; ax_ = tx + 2; by = oy + 0; bx_ = tx + 0; } // SE,NW

            const uint64_t cc = s_g2_64[((oy + 1) * 34 + (tx + 1)) * 2 + comp];
            const uint64_t va = s_g2_64[(ay * 34 + ax_) * 2 + comp];
            const uint64_t vb = s_g2_64[(by * 34 + bx_) * 2 + comp];

            float sv = 0.0f;
            if (cc > va && cc > vb)
                sv = sqrtf((float)cc) * 0x1p-29f;   // g2 is Q0.58
            sup[comp] = sv;
        }

        g_sup2[(size_t)p * IMG_HW + (size_t)(y0 + oy) * IMG_W + (x0 + tx)] =
            make_float2(sup[0], sup[1]);
        vmax = fmaxf(vmax, fmaxf(sup[0], sup[1]));
    }

    // block max (sup >= 0 -> uint order == float order); min is provably 0
#pragma unroll
    for (int off = 16; off > 0; off >>= 1)
        vmax = fmaxf(vmax, __shfl_xor_sync(0xFFFFFFFF, vmax, off));
    const int wid = tid >> 5;
    if ((tid & 31) == 0) smax[wid] = vmax;
    __syncthreads();
    if (tid == 0) {
        float bmax = smax[0];
#pragma unroll
        for (int i = 1; i < NTHR / 32; i++) bmax = fmaxf(bmax, smax[i]);
        atomicMax(&g_max_bits, __float_as_uint(bmax));
    }
}

// ---------------------------------------------------------------------------
// Fused back: 4 batches (2 sup planes) per block; resets g_max at the end
// ---------------------------------------------------------------------------
__global__ __launch_bounds__(NTHR, 4) void fused_back_kernel(float* __restrict__ out) {
    __shared__ float2   s_sup[2][18][34];
    __shared__ uint64_t s_str[2][18][34];

    const int x0 = blockIdx.x * BTX;
    const int y0 = blockIdx.y * BTY;
    const int q  = blockIdx.z;
    const int tid = threadIdx.x;
    const float2* sup0 = g_sup2 + (size_t)(2 * q)     * IMG_HW;
    const float2* sup1 = g_sup2 + (size_t)(2 * q + 1) * IMG_HW;

    // min(sup) == 0 exactly (NMS always suppresses some pixels)
    const float mx   = __uint_as_float(g_max_bits);
    const float high = mx * 0.25f;
    const float low  = mx * 0.1f;

#pragma unroll 2
    for (int i = tid; i < 18 * 34; i += NTHR) {
        const int yy = i / 34, xx = i - yy * 34;
        const int gx = refl(x0 - 1 + xx, IMG_W);
        const int gy = refl(y0 - 1 + yy, IMG_H);
        const int gi = gy * IMG_W + gx;
        const float2 a = sup0[gi];
        const float2 b = sup1[gi];
        s_sup[0][yy][xx] = a;
        s_sup[1][yy][xx] = b;
        s_str[0][yy][xx] = pack2(sigm(100.0f * (a.x - high)),
                                 sigm(100.0f * (a.y - high)));
        s_str[1][yy][xx] = pack2(sigm(100.0f * (b.x - high)),
                                 sigm(100.0f * (b.y - high)));
    }
    __syncthreads();   // also guarantees every thread consumed g_max_bits

    const int tx = tid & (BTX - 1);
    const int ty = tid >> 5;
    const size_t idx = (size_t)(y0 + ty) * IMG_W + (x0 + tx);

#pragma unroll
    for (int j = 0; j < 2; j++) {
        uint64_t hs = s_str[j][ty + 0][tx + 0];
        hs = f2add(hs, s_str[j][ty + 0][tx + 1]);
        hs = f2add(hs, s_str[j][ty + 0][tx + 2]);
        hs = f2add(hs, s_str[j][ty + 1][tx + 0]);
        hs = f2add(hs, s_str[j][ty + 1][tx + 1]);
        hs = f2add(hs, s_str[j][ty + 1][tx + 2]);
        hs = f2add(hs, s_str[j][ty + 2][tx + 0]);
        hs = f2add(hs, s_str[j][ty + 2][tx + 1]);
        hs = f2add(hs, s_str[j][ty + 2][tx + 2]);

        const uint64_t sc = s_str[j][ty + 1][tx + 1];
        const float2  sv  = s_sup[j][ty + 1][tx + 1];

        const float s0 = plo(sc), s1 = phi(sc);
        const float w0 = sigm(100.0f * (sv.x - low)) * (1.0f - s0);
        const float w1 = sigm(100.0f * (sv.y - low)) * (1.0f - s1);
        const float m0 = s0 + w0 * sigm(100.0f * (plo(hs) - 0.5f));
        const float m1 = s1 + w1 * sigm(100.0f * (phi(hs) - 0.5f));

        out[(size_t)(4 * q + 2 * j)     * IMG_HW + idx] = m0;
        out[(size_t)(4 * q + 2 * j + 1) * IMG_HW + idx] = m1;
    }

    // last-finishing block resets scalars for the next graph replay
    if (tid == 0) {
        const unsigned t = atomicAdd(&g_done, 1u);
        if (t == (unsigned)(NBLOCKS_BACK - 1)) {
            g_max_bits = 0u;
            g_done = 0u;
        }
    }
}

// ---------------------------------------------------------------------------
extern "C" void kernel_launch(void* const* d_in, const int* in_sizes, int n_in,
                              void* d_out, int out_size) {
    const float* image = (const float*)d_in[0];
    float* out = (float*)d_out;

    dim3 grdF(IMG_W / TX, IMG_H / TY, NPAIR);
    fused_front_kernel<<<grdF, NTHR>>>(image);

    dim3 grdB(IMG_W / BTX, IMG_H / BTY, 2);
    fused_back_kernel<<<grdB, NTHR>>>(out);
}

// round 16
// speedup vs baseline: 1.0963x; 1.0963x over previous
#include <cuda_runtime.h>
#include <math.h>
#include <stdint.h>

#define IMG_W 1024
#define IMG_H 1024
#define IMG_B 8
#define IMG_HW (IMG_H * IMG_W)

#define TX 32
#define TY 32
#define NTHR 512
#define NPAIR 4
#define BTX 32
#define BTY 16
#define NBLOCKS_BACK ((IMG_W / BTX) * (IMG_H / BTY) * 2)

// ---------------------------------------------------------------------------
// Scratch (allocation-free rule: __device__ globals; zero-initialized)
// ---------------------------------------------------------------------------
__device__ float2 g_sup2[(size_t)NPAIR * IMG_HW];
__device__ unsigned int g_max_bits;   // reset by last back block each launch
__device__ unsigned int g_done;

__device__ __forceinline__ int refl(int i, int n) {
    if (i < 0) i = -i;
    if (i >= n) i = 2 * n - 2 - i;
    return i;
}

// fast sigmoid (smooth output path only)
__device__ __forceinline__ float sigm(float x) {
    float e = __expf(-x);
    float d = 1.0f + e;
    float r; asm("rcp.approx.f32 %0, %1;" : "=f"(r) : "f"(d));
    return r;
}

// packed helpers for the back kernel
__device__ __forceinline__ uint64_t f2add(uint64_t a, uint64_t b) {
    uint64_t r; asm("add.rn.f32x2 %0, %1, %2;" : "=l"(r) : "l"(a), "l"(b)); return r;
}
__device__ __forceinline__ uint64_t pack2(float lo, float hi) {
    return ((uint64_t)__float_as_uint(hi) << 32) | (uint64_t)__float_as_uint(lo);
}
__device__ __forceinline__ float plo(uint64_t v) { return __uint_as_float((unsigned)v); }
__device__ __forceinline__ float phi(uint64_t v) { return __uint_as_float((unsigned)(v >> 32)); }

// ---------------------------------------------------------------------------
// Exact fp32 -> Q0.27 u32 (round-to-nearest; mantissa shift, no fp rounding)
// ---------------------------------------------------------------------------
__device__ __forceinline__ unsigned q27(float v) {
    const unsigned bits = __float_as_uint(v);       // v >= 0
    const int e = (int)(bits >> 23);
    const unsigned m = (bits & 0x7fffffu) | 0x800000u;
    const int sh = e - 123;                         // v*2^27 = m * 2^sh
    if (sh >= 0) return m << sh;                    // v < 1 -> sh <= 3
    const int k = -sh;
    return (k < 32) ? ((m + (1u << (k - 1))) >> k) : 0u;
}

// Exact fp32 weight -> Q0.32 u32 (weights have ulp >= 2^-29: exact)
__device__ __forceinline__ unsigned wq32(float w) {
    const unsigned bits = __float_as_uint(w);
    const unsigned m = (bits & 0x7fffffu) | 0x800000u;
    const int sh = (int)(bits >> 23) - 118;
    return m << sh;
}

// round(tan(22.5 deg) * 2^32)
#define T1U 1779033704u

// ---------------------------------------------------------------------------
// Shared overlay (bytes), peak 34688 (static):
//   img (40x40 u64, 12800) @ 0      live S1-S2   (also viewed as [40][20] uint4)
//   row (40x36 u64, 11520) @ 12800  live S2-S3
//   sm  (36x36 u64, 10368) @ 24320  live S3-SD
//   g2  (34x34 x2 u64, 18496) @ 0   live SD-SE
//   bin (34x34 u8,   1156) @ 18496  live SD-SE
// ---------------------------------------------------------------------------
#define OFF_IMG 0
#define OFF_ROW 12800
#define OFF_SM  24320
#define OFF_G2  0
#define OFF_BIN 18496
#define SBUF_SZ 34688

// ---------------------------------------------------------------------------
// Fused front (integer pipeline, register-blocked stages)
// ---------------------------------------------------------------------------
__global__ __launch_bounds__(NTHR, 4) void fused_front_kernel(const float* __restrict__ img) {
    __shared__ __align__(16) unsigned char sbuf[SBUF_SZ];
    __shared__ float smax[NTHR / 32];

    uint64_t (*s_img)[40]  = (uint64_t(*)[40])(sbuf + OFF_IMG);
    uint4    (*s_img4)[20] = (uint4(*)[20])(sbuf + OFF_IMG);   // 2 pixels / uint4
    uint64_t (*s_row)[36]  = (uint64_t(*)[36])(sbuf + OFF_ROW);
    uint64_t (*s_sm )[36]  = (uint64_t(*)[36])(sbuf + OFF_SM);
    uint64_t* s_g2_64 = (uint64_t*)(sbuf + OFF_G2);            // [(jy*34+jx)*2+c]
    unsigned char (*s_bin)[34] = (unsigned char(*)[34])(sbuf + OFF_BIN);

    const int x0 = blockIdx.x * TX;
    const int y0 = blockIdx.y * TY;
    const int p  = blockIdx.z;
    const float* p0 = img + (size_t)(2 * p)     * IMG_HW;
    const float* p1 = img + (size_t)(2 * p + 1) * IMG_HW;
    const int tid = threadIdx.x;

    const float w5[5] = {0.054488684549640294f, 0.24420134200323337f,
                         0.4026199468935272f,  0.24420134200323337f,
                         0.054488684549640294f};
    unsigned W[5];
#pragma unroll
    for (int k = 0; k < 5; k++) W[k] = wq32(w5[k]);

    // ---- S1: load + quantize image tile 40x40 (reflect once) ----
#pragma unroll 2
    for (int i = tid; i < 40 * 40; i += NTHR) {
        const int yy = i / 40, xx = i - yy * 40;
        const int gx = refl(x0 - 4 + xx, IMG_W);
        const int gy = refl(y0 - 4 + yy, IMG_H);
        const int gi = gy * IMG_W + gx;
        const unsigned a = q27(p0[gi]);
        const unsigned b = q27(p1[gi]);
        s_img[yy][xx] = ((uint64_t)b << 32) | a;
    }
    __syncthreads();

    // ---- S2: row gaussian (x); 2 outputs/thread via 3 LDS.128 ----
    // outputs (ry, 2g) and (ry, 2g+1) from pixels 2g..2g+5 of row ry
#pragma unroll 2
    for (int i = tid; i < 40 * 18; i += NTHR) {
        const int ry = i / 18, g = i - ry * 18;
        const uint4 q0 = s_img4[ry][g];
        const uint4 q1 = s_img4[ry][g + 1];
        const uint4 q2 = s_img4[ry][g + 2];

        uint64_t a;
        a = (uint64_t)W[0] * q0.x + (uint64_t)W[1] * q0.z + (uint64_t)W[2] * q1.x
          + (uint64_t)W[3] * q1.z + (uint64_t)W[4] * q2.x;
        const unsigned r00 = (unsigned)((a + (1u << 29)) >> 30);
        a = (uint64_t)W[0] * q0.y + (uint64_t)W[1] * q0.w + (uint64_t)W[2] * q1.y
          + (uint64_t)W[3] * q1.w + (uint64_t)W[4] * q2.y;
        const unsigned r01 = (unsigned)((a + (1u << 29)) >> 30);
        a = (uint64_t)W[0] * q0.z + (uint64_t)W[1] * q1.x + (uint64_t)W[2] * q1.z
          + (uint64_t)W[3] * q2.x + (uint64_t)W[4] * q2.z;
        const unsigned r10 = (unsigned)((a + (1u << 29)) >> 30);
        a = (uint64_t)W[0] * q0.w + (uint64_t)W[1] * q1.y + (uint64_t)W[2] * q1.w
          + (uint64_t)W[3] * q2.y + (uint64_t)W[4] * q2.w;
        const unsigned r11 = (unsigned)((a + (1u << 29)) >> 30);

        s_row[ry][2 * g]     = ((uint64_t)r01 << 32) | r00;
        s_row[ry][2 * g + 1] = ((uint64_t)r11 << 32) | r10;
    }
    __syncthreads();

    // ---- S3: column gaussian (y); 4 outputs/thread, conflict-free column loads ----
    if (tid < 9 * 36) {
        const int sx = tid % 36, sy0 = (tid / 36) * 4;
        uint64_t h[8];
#pragma unroll
        for (int k = 0; k < 8; k++) h[k] = s_row[sy0 + k][sx];
#pragma unroll
        for (int j = 0; j < 4; j++) {
            uint64_t a0 = 0, a1 = 0;
#pragma unroll
            for (int k = 0; k < 5; k++) {
                const uint64_t v = h[j + k];
                a0 += (uint64_t)W[k] * (unsigned)v;
                a1 += (uint64_t)W[k] * (unsigned)(v >> 32);
            }
            const unsigned r0 = (unsigned)((a0 + (1u << 31)) >> 32);
            const unsigned r1 = (unsigned)((a1 + (1u << 31)) >> 32);
            s_sm[sy0 + j][sx] = ((uint64_t)r1 << 32) | r0;
        }
    }
    __syncthreads();

    // ---- SD: sobel + g2 + bins; 2 outputs/thread (y-blocked, d/s factored) ----
#pragma unroll 2
    for (int i = tid; i < 17 * 34; i += NTHR) {
        const int jx = i % 34, jy0 = (i / 34) * 2;
        int d[2][4], s[2][4];   // [lane][row]
#pragma unroll
        for (int r = 0; r < 4; r++) {
            const uint64_t u0 = s_sm[jy0 + r][jx + 0];
            const uint64_t u1 = s_sm[jy0 + r][jx + 1];
            const uint64_t u2 = s_sm[jy0 + r][jx + 2];
#pragma unroll
            for (int c = 0; c < 2; c++) {
                const int v0 = (int)(unsigned)(u0 >> (c * 32));
                const int v1 = (int)(unsigned)(u1 >> (c * 32));
                const int v2 = (int)(unsigned)(u2 >> (c * 32));
                d[c][r] = v2 - v0;
                s[c][r] = v0 + 2 * v1 + v2;
            }
        }
#pragma unroll
        for (int o = 0; o < 2; o++) {
            const int jy = jy0 + o;
            const bool interior = (jy >= 1 && jy <= TY && jx >= 1 && jx <= TX);
            unsigned char pb = 0;
#pragma unroll
            for (int c = 0; c < 2; c++) {
                const int gx = d[c][o] + 2 * d[c][o + 1] + d[c][o + 2];
                const int gy = s[c][o] - s[c][o + 2];
                s_g2_64[(jy * 34 + jx) * 2 + c] =
                    (uint64_t)((long long)gx * gx + (long long)gy * gy);
                if (interior) {
                    const unsigned ax = (unsigned)(gx < 0 ? -gx : gx);
                    const unsigned ay = (unsigned)(gy < 0 ? -gy : gy);
                    unsigned char bin;
                    if (((uint64_t)ay << 32) < (uint64_t)T1U * ax)       bin = 0; // E/W
                    else if (((uint64_t)ax << 32) <= (uint64_t)T1U * ay) bin = 2; // N/S
                    else bin = ((gx > 0) == (gy > 0)) ? 1 : 3;                    // SW/NE : SE/NW
                    pb |= bin << (2 * c);
                }
            }
            if (interior) s_bin[jy][jx] = pb;
        }
    }
    __syncthreads();

    // ---- SE: NMS (exact u64 compares) + sup + block max ----
    const int tx = tid & (TX - 1);
    const int ty = tid >> 5;   // 0..15

    float vmax = 0.0f;
#pragma unroll
    for (int half = 0; half < 2; half++) {
        const int oy = ty + half * 16;
        const unsigned char pb2 = s_bin[oy + 1][tx + 1];

        float sup[2];
#pragma unroll
        for (int comp = 0; comp < 2; comp++) {
            const int bin = (pb2 >> (2 * comp)) & 3;
            int ay, ax_, by, bx_;
            if (bin == 0)      { ay = oy + 1; ax_ = tx + 2; by = oy + 1; bx_ = tx + 0; } // E,W
            else if (bin == 2) { ay = oy + 0; ax_ = tx + 1; by = oy + 2; bx_ = tx + 1; } // N,S
            else if (bin == 1) { ay = oy + 2; ax_ = tx + 0; by = oy + 0; bx_ = tx + 2; } // SW,NE
            else               { ay = oy + 2; ax_ = tx + 2; by = oy + 0; bx_ = tx + 0; } // SE,NW

            const uint64_t cc = s_g2_64[((oy + 1) * 34 + (tx + 1)) * 2 + comp];
            const uint64_t va = s_g2_64[(ay * 34 + ax_) * 2 + comp];
            const uint64_t vb = s_g2_64[(by * 34 + bx_) * 2 + comp];

            float sv = 0.0f;
            if (cc > va && cc > vb)
                sv = sqrtf((float)cc) * 0x1p-29f;   // g2 is Q0.58
            sup[comp] = sv;
        }

        g_sup2[(size_t)p * IMG_HW + (size_t)(y0 + oy) * IMG_W + (x0 + tx)] =
            make_float2(sup[0], sup[1]);
        vmax = fmaxf(vmax, fmaxf(sup[0], sup[1]));
    }

    // block max (sup >= 0 -> uint order == float order); min is provably 0
#pragma unroll
    for (int off = 16; off > 0; off >>= 1)
        vmax = fmaxf(vmax, __shfl_xor_sync(0xFFFFFFFF, vmax, off));
    const int wid = tid >> 5;
    if ((tid & 31) == 0) smax[wid] = vmax;
    __syncthreads();
    if (tid == 0) {
        float bmax = smax[0];
#pragma unroll
        for (int i = 1; i < NTHR / 32; i++) bmax = fmaxf(bmax, smax[i]);
        atomicMax(&g_max_bits, __float_as_uint(bmax));
    }
}

// ---------------------------------------------------------------------------
// Fused back: 4 batches (2 sup planes) per block; resets g_max at the end
// ---------------------------------------------------------------------------
__global__ __launch_bounds__(NTHR, 4) void fused_back_kernel(float* __restrict__ out) {
    __shared__ float2   s_sup[2][18][34];
    __shared__ uint64_t s_str[2][18][34];

    const int x0 = blockIdx.x * BTX;
    const int y0 = blockIdx.y * BTY;
    const int q  = blockIdx.z;
    const int tid = threadIdx.x;
    const float2* sup0 = g_sup2 + (size_t)(2 * q)     * IMG_HW;
    const float2* sup1 = g_sup2 + (size_t)(2 * q + 1) * IMG_HW;

    // min(sup) == 0 exactly (NMS always suppresses some pixels)
    const float mx   = __uint_as_float(g_max_bits);
    const float high = mx * 0.25f;
    const float low  = mx * 0.1f;

#pragma unroll 2
    for (int i = tid; i < 18 * 34; i += NTHR) {
        const int yy = i / 34, xx = i - yy * 34;
        const int gx = refl(x0 - 1 + xx, IMG_W);
        const int gy = refl(y0 - 1 + yy, IMG_H);
        const int gi = gy * IMG_W + gx;
        const float2 a = sup0[gi];
        const float2 b = sup1[gi];
        s_sup[0][yy][xx] = a;
        s_sup[1][yy][xx] = b;
        s_str[0][yy][xx] = pack2(sigm(100.0f * (a.x - high)),
                                 sigm(100.0f * (a.y - high)));
        s_str[1][yy][xx] = pack2(sigm(100.0f * (b.x - high)),
                                 sigm(100.0f * (b.y - high)));
    }
    __syncthreads();   // also guarantees every thread consumed g_max_bits

    const int tx = tid & (BTX - 1);
    const int ty = tid >> 5;
    const size_t idx = (size_t)(y0 + ty) * IMG_W + (x0 + tx);

#pragma unroll
    for (int j = 0; j < 2; j++) {
        uint64_t hs = s_str[j][ty + 0][tx + 0];
        hs = f2add(hs, s_str[j][ty + 0][tx + 1]);
        hs = f2add(hs, s_str[j][ty + 0][tx + 2]);
        hs = f2add(hs, s_str[j][ty + 1][tx + 0]);
        hs = f2add(hs, s_str[j][ty + 1][tx + 1]);
        hs = f2add(hs, s_str[j][ty + 1][tx + 2]);
        hs = f2add(hs, s_str[j][ty + 2][tx + 0]);
        hs = f2add(hs, s_str[j][ty + 2][tx + 1]);
        hs = f2add(hs, s_str[j][ty + 2][tx + 2]);

        const uint64_t sc = s_str[j][ty + 1][tx + 1];
        const float2  sv  = s_sup[j][ty + 1][tx + 1];

        const float s0 = plo(sc), s1 = phi(sc);
        const float w0 = sigm(100.0f * (sv.x - low)) * (1.0f - s0);
        const float w1 = sigm(100.0f * (sv.y - low)) * (1.0f - s1);
        const float m0 = s0 + w0 * sigm(100.0f * (plo(hs) - 0.5f));
        const float m1 = s1 + w1 * sigm(100.0f * (phi(hs) - 0.5f));

        out[(size_t)(4 * q + 2 * j)     * IMG_HW + idx] = m0;
        out[(size_t)(4 * q + 2 * j + 1) * IMG_HW + idx] = m1;
    }

    // last-finishing block resets scalars for the next graph replay
    if (tid == 0) {
        const unsigned t = atomicAdd(&g_done, 1u);
        if (t == (unsigned)(NBLOCKS_BACK - 1)) {
            g_max_bits = 0u;
            g_done = 0u;
        }
    }
}

// ---------------------------------------------------------------------------
extern "C" void kernel_launch(void* const* d_in, const int* in_sizes, int n_in,
                              void* d_out, int out_size) {
    const float* image = (const float*)d_in[0];
    float* out = (float*)d_out;

    dim3 grdF(IMG_W / TX, IMG_H / TY, NPAIR);
    fused_front_kernel<<<grdF, NTHR>>>(image);

    dim3 grdB(IMG_W / BTX, IMG_H / BTY, 2);
    fused_back_kernel<<<grdB, NTHR>>>(out);
}